// round 13
// baseline (speedup 1.0000x reference)
#include <cuda_runtime.h>
#include <math.h>

// GRU problem constants
#define T_SEQ 1024
#define BATCH 32
#define HID   512
#define H3    1536   // 3*HID
#define LAYERS 3

// ---------------------------------------------------------------------------
// Scratch (device globals — no runtime allocation allowed)
// ---------------------------------------------------------------------------
__device__ float g_xi[2][T_SEQ][H3][BATCH];     // [dir][t][gate_row][batch]
__device__ float g_y[2][T_SEQ][BATCH][2 * HID]; // layer outputs (2 buffers)
__device__ float g_h[2][2][BATCH][HID];         // h double buffer [buf][dir][b][k]
__device__ int   g_flag[2][4][32];              // [dir][group][cta] epoch flags

typedef unsigned long long ull;

// ---------------------------------------------------------------------------
// f32x2 packed-FMA helpers (sm_100+; only reachable via PTX)
// ---------------------------------------------------------------------------
__device__ __forceinline__ ull dup2(float x) {
    ull r;
    asm("mov.b64 %0, {%1, %1};" : "=l"(r) : "f"(x));
    return r;
}
__device__ __forceinline__ void ffma2(ull& d, ull a, ull b) {
    asm("fma.rn.f32x2 %0, %1, %2, %0;" : "+l"(d) : "l"(a), "l"(b));
}
__device__ __forceinline__ float2 unpk(ull v) {
    float2 f;
    asm("mov.b64 {%0, %1}, %2;" : "=f"(f.x), "=f"(f.y) : "l"(v));
    return f;
}

// ---------------------------------------------------------------------------
// Zero the flag array (runs once per graph replay, before gru0)
// ---------------------------------------------------------------------------
__global__ void zero_bar_kernel() {
    int i = threadIdx.x;
    if (i < 2 * 4 * 32) ((int*)g_flag)[i] = 0;
}

// ---------------------------------------------------------------------------
// Input projection v4: 128j x 256m tile, 256 threads, 16m x 8j per thread,
// register double-buffered global loads, f32x2 packed FMA.
// Per SMSP per kk: LDS ~192 cyc vs FMA 512 cyc -> solidly FMA-bound.
// ---------------------------------------------------------------------------
__global__ __launch_bounds__(256) void proj_kernel(
    const float* __restrict__ x0,
    const float* __restrict__ W,      // (2, 1536, K)
    const float* __restrict__ bih,    // (2, 1536)
    int K, int src)
{
    const float* A = (src == 0) ? x0 : &g_y[src - 1][0][0][0];

    int d  = blockIdx.z;
    int n0 = blockIdx.x * 128;  // gate-row tile
    int m0 = blockIdx.y * 256;  // (t,b) row tile
    const float* Wd = W + (size_t)d * H3 * K;
    const float* bd = bih + d * H3;

    __shared__ float As[16][256];
    __shared__ float Bs[16][128];

    int tid = threadIdx.x;
    int tx  = tid & 15;
    int ty  = tid >> 4;

    // Staging: A = 1024 float4 (4/thread), B = 512 float4 (2/thread)
    int arow[4], aq[4];
#pragma unroll
    for (int i = 0; i < 4; i++) {
        int idx = i * 256 + tid;
        arow[i] = idx >> 2;
        aq[i]   = (idx & 3) << 2;
    }
    int brow[2], bq[2];
#pragma unroll
    for (int i = 0; i < 2; i++) {
        int idx = i * 256 + tid;
        brow[i] = idx >> 2;
        bq[i]   = (idx & 3) << 2;
    }

    ull acc[16][4];
#pragma unroll
    for (int i = 0; i < 16; i++)
#pragma unroll
        for (int j = 0; j < 4; j++) acc[i][j] = 0ull;

    float4 a_nx[4], b_nx[2];
#pragma unroll
    for (int i = 0; i < 4; i++)
        a_nx[i] = *(const float4*)&A[(size_t)(m0 + arow[i]) * K + aq[i]];
#pragma unroll
    for (int i = 0; i < 2; i++)
        b_nx[i] = *(const float4*)&Wd[(size_t)(n0 + brow[i]) * K + bq[i]];

    for (int k0 = 0; k0 < K; k0 += 16) {
#pragma unroll
        for (int i = 0; i < 4; i++) {
            As[aq[i] + 0][arow[i]] = a_nx[i].x;
            As[aq[i] + 1][arow[i]] = a_nx[i].y;
            As[aq[i] + 2][arow[i]] = a_nx[i].z;
            As[aq[i] + 3][arow[i]] = a_nx[i].w;
        }
#pragma unroll
        for (int i = 0; i < 2; i++) {
            Bs[bq[i] + 0][brow[i]] = b_nx[i].x;
            Bs[bq[i] + 1][brow[i]] = b_nx[i].y;
            Bs[bq[i] + 2][brow[i]] = b_nx[i].z;
            Bs[bq[i] + 3][brow[i]] = b_nx[i].w;
        }
        __syncthreads();

        if (k0 + 16 < K) {
            int kn = k0 + 16;
#pragma unroll
            for (int i = 0; i < 4; i++)
                a_nx[i] = *(const float4*)&A[(size_t)(m0 + arow[i]) * K + kn + aq[i]];
#pragma unroll
            for (int i = 0; i < 2; i++)
                b_nx[i] = *(const float4*)&Wd[(size_t)(n0 + brow[i]) * K + kn + bq[i]];
        }

#pragma unroll
        for (int kk = 0; kk < 16; kk++) {
            ulonglong2 b0 = *(const ulonglong2*)&Bs[kk][tx * 4];
            ulonglong2 b1 = *(const ulonglong2*)&Bs[kk][64 + tx * 4];
#pragma unroll
            for (int c = 0; c < 4; c++) {
                float4 af = *(const float4*)&As[kk][c * 64 + ty * 4];
                ull a0 = dup2(af.x);
                ull a1 = dup2(af.y);
                ull a2 = dup2(af.z);
                ull a3 = dup2(af.w);
                ffma2(acc[c * 4 + 0][0], a0, b0.x); ffma2(acc[c * 4 + 0][1], a0, b0.y);
                ffma2(acc[c * 4 + 0][2], a0, b1.x); ffma2(acc[c * 4 + 0][3], a0, b1.y);
                ffma2(acc[c * 4 + 1][0], a1, b0.x); ffma2(acc[c * 4 + 1][1], a1, b0.y);
                ffma2(acc[c * 4 + 1][2], a1, b1.x); ffma2(acc[c * 4 + 1][3], a1, b1.y);
                ffma2(acc[c * 4 + 2][0], a2, b0.x); ffma2(acc[c * 4 + 2][1], a2, b0.y);
                ffma2(acc[c * 4 + 2][2], a2, b1.x); ffma2(acc[c * 4 + 2][3], a2, b1.y);
                ffma2(acc[c * 4 + 3][0], a3, b0.x); ffma2(acc[c * 4 + 3][1], a3, b0.y);
                ffma2(acc[c * 4 + 3][2], a3, b1.x); ffma2(acc[c * 4 + 3][3], a3, b1.y);
            }
        }
        __syncthreads();
    }

#pragma unroll
    for (int c = 0; c < 4; c++) {
#pragma unroll
        for (int i = 0; i < 4; i++) {
            int m = m0 + c * 64 + ty * 4 + i;
            int t = m >> 5;
            int b = m & 31;
#pragma unroll
            for (int jp = 0; jp < 4; jp++) {
                int g = n0 + ((jp < 2) ? (tx * 4 + jp * 2)
                                       : (64 + tx * 4 + (jp - 2) * 2));
                float2 cv = unpk(acc[c * 4 + i][jp]);
                g_xi[d][t][g + 0][b] = cv.x + bd[g + 0];
                g_xi[d][t][g + 1][b] = cv.y + bd[g + 1];
            }
        }
    }
}

// ---------------------------------------------------------------------------
// Persistent recurrent kernel (R11 structure — best measured variant).
// Register-resident W_hh; single end-of-step flag post + wait; __expf gates.
// ---------------------------------------------------------------------------
__global__ __launch_bounds__(256) void gru_layer_kernel(
    const float* __restrict__ whh,   // (2, 1536, 512)
    const float* __restrict__ bhh,   // (2, 1536)
    float* __restrict__ dout,        // (6, 32, 512)
    int layer, int ydst)
{
    __shared__ float sH[8 * HID];    // 16KB h staging [b_in_group][k]

    int ctax = blockIdx.x;           // 0..15 : j-slice (32 j each)
    int grp  = blockIdx.y;           // 0..3  : batch octet
    int d    = blockIdx.z;           // direction
    int tid  = threadIdx.x;
    int w    = tid >> 5;
    int l    = tid & 31;
    int lj   = l & 3;                // j-row within quad
    int lks  = l >> 2;               // k-slice 0..7
    int j    = ctax * 32 + w * 4 + lj;   // global j (this thread's row)
    int b_ep = grp * 8 + lks;        // epilogue batch

    // ---- Load W_hh into registers (once per layer) ----
    ull Wr[32], Wz[32], Wn[32];
    {
        const float* wd = whh + (size_t)d * H3 * HID;
        const float* pr = &wd[(size_t)(0 * 512 + j) * 512 + lks * 4];
        const float* pz = &wd[(size_t)(1 * 512 + j) * 512 + lks * 4];
        const float* pn = &wd[(size_t)(2 * 512 + j) * 512 + lks * 4];
#pragma unroll
        for (int i = 0; i < 16; i++) {
            ulonglong2 v;
            v = *(const ulonglong2*)&pr[i * 32];
            Wr[2 * i] = v.x; Wr[2 * i + 1] = v.y;
            v = *(const ulonglong2*)&pz[i * 32];
            Wz[2 * i] = v.x; Wz[2 * i + 1] = v.y;
            v = *(const ulonglong2*)&pn[i * 32];
            Wn[2 * i] = v.x; Wn[2 * i + 1] = v.y;
        }
    }
    const float* bd = bhh + d * H3;
    float br = bd[j], bz = bd[512 + j], bn = bd[1024 + j];

    volatile int* flags = &g_flag[d][grp][0];
    float hold = 0.f;
    int t0 = d ? (T_SEQ - 1) : 0;
    float xr = g_xi[d][t0][j][b_ep];
    float xz = g_xi[d][t0][512 + j][b_ep];
    float xn = g_xi[d][t0][1024 + j][b_ep];

    for (int s = 0; s < T_SEQ; s++) {
        int t = d ? (T_SEQ - 1 - s) : s;

        float arS = 0.f, azS = 0.f, anS = 0.f;
        if (s > 0) {
            // Stage group's h: 8 rows x 512 = 1024 float4 -> 4 per thread
            const float* hin = &g_h[s & 1][d][grp * 8][0];
#pragma unroll
            for (int it = 0; it < 4; it++) {
                int idx = it * 256 + tid;            // float4 units, 0..1023
                float4 v = __ldcg((const float4*)&hin[idx << 2]);
                *(float4*)&sH[idx << 2] = v;
            }
            __syncthreads();

            // GEMV: per batch, partial over this thread's strided k-slice,
            // butterfly-reduce over lks; keep the b == lks result.
            for (int b = 0; b < 8; b++) {
                const float* hp = &sH[b * HID + lks * 4];
                ull a0 = 0ull, a1 = 0ull, a2 = 0ull;
#pragma unroll
                for (int i = 0; i < 16; i++) {
                    ulonglong2 hh = *(const ulonglong2*)&hp[i * 32];
                    ffma2(a0, Wr[2 * i], hh.x); ffma2(a0, Wr[2 * i + 1], hh.y);
                    ffma2(a1, Wz[2 * i], hh.x); ffma2(a1, Wz[2 * i + 1], hh.y);
                    ffma2(a2, Wn[2 * i], hh.x); ffma2(a2, Wn[2 * i + 1], hh.y);
                }
                float2 f0 = unpk(a0), f1 = unpk(a1), f2 = unpk(a2);
                float ar = f0.x + f0.y;
                float az = f1.x + f1.y;
                float an = f2.x + f2.y;
#pragma unroll
                for (int m = 4; m <= 16; m <<= 1) {
                    ar += __shfl_xor_sync(0xffffffffu, ar, m);
                    az += __shfl_xor_sync(0xffffffffu, az, m);
                    an += __shfl_xor_sync(0xffffffffu, an, m);
                }
                if (lks == b) { arS = ar; azS = az; anS = an; }
            }
        }

        float r = 1.f / (1.f + __expf(-(xr + arS + br)));
        float z = 1.f / (1.f + __expf(-(xz + azS + bz)));
        float n = tanhf(xn + r * (anS + bn));
        float hnew = (1.f - z) * n + z * hold;
        hold = hnew;

        g_h[(s & 1) ^ 1][d][b_ep][j] = hnew;
        g_y[ydst][t][b_ep][d * HID + j] = hnew;

        if (s == T_SEQ - 1) {
            dout[((layer * 2 + d) * BATCH + b_ep) * HID + j] = hnew;
            break;   // nothing consumes h after the last step
        }

        // ---- Group barrier: 16 CTAs, per-CTA epoch flags ----
        __syncthreads();                 // h stores issued; sH reads done
        int e = layer * T_SEQ + s + 1;   // monotonic across layers
        if (tid == 0) {
            __threadfence();             // order this CTA's h stores
            flags[ctax] = e;
        }
        // Prefetch next step's Xi while flags propagate
        int tn = d ? (T_SEQ - 2 - s) : (s + 1);
        float nxr = g_xi[d][tn][j][b_ep];
        float nxz = g_xi[d][tn][512 + j][b_ep];
        float nxn = g_xi[d][tn][1024 + j][b_ep];
        if (tid < 16) {
            while (flags[tid] < e) { }
            __threadfence();             // acquire side
        }
        __syncthreads();
        xr = nxr; xz = nxz; xn = nxn;
    }
}

// ---------------------------------------------------------------------------
// kernel_launch: proj0, zero, gru0, proj1, gru1, proj2, gru2
// (7 graph nodes; ncu -s 5 -c 1 lands on proj2)
// ---------------------------------------------------------------------------
extern "C" void kernel_launch(void* const* d_in, const int* in_sizes, int n_in,
                              void* d_out, int out_size)
{
    const float* x        = (const float*)d_in[0];
    const float* w_ih_l0  = (const float*)d_in[1];
    const float* w_hh_l0  = (const float*)d_in[2];
    const float* b_ih_l0  = (const float*)d_in[3];
    const float* b_hh_l0  = (const float*)d_in[4];
    const float* w_ih_lr  = (const float*)d_in[5];
    const float* w_hh_lr  = (const float*)d_in[6];
    const float* b_ih_lr  = (const float*)d_in[7];
    const float* b_hh_lr  = (const float*)d_in[8];
    float* out = (float*)d_out;

    const float* WI[LAYERS];
    const float* WH[LAYERS];
    const float* BI[LAYERS];
    const float* BH[LAYERS];
    int KK[LAYERS], SRC[LAYERS], YD[LAYERS];
    for (int L = 0; L < LAYERS; L++) {
        if (L == 0) {
            WI[L] = w_ih_l0; WH[L] = w_hh_l0; BI[L] = b_ih_l0; BH[L] = b_hh_l0;
            KK[L] = 256; SRC[L] = 0;
        } else {
            WI[L] = w_ih_lr + (size_t)(L - 1) * 2 * H3 * 1024;
            WH[L] = w_hh_lr + (size_t)(L - 1) * 2 * H3 * HID;
            BI[L] = b_ih_lr + (L - 1) * 2 * H3;
            BH[L] = b_hh_lr + (L - 1) * 2 * H3;
            KK[L] = 1024; SRC[L] = L;
        }
        YD[L] = (L == 1) ? 1 : 0;   // L0->buf0, L1->buf1, L2->buf0 (unused)
    }

    dim3 pg(H3 / 128, (T_SEQ * BATCH) / 256, 2);
    dim3 gg(16, 4, 2);   // (j-slice, group, dir)

    proj_kernel<<<pg, 256>>>(x, WI[0], BI[0], KK[0], SRC[0]);
    zero_bar_kernel<<<1, 256>>>();

    gru_layer_kernel<<<gg, 256>>>(WH[0], BH[0], out, 0, YD[0]);
    proj_kernel<<<pg, 256>>>(x, WI[1], BI[1], KK[1], SRC[1]);
    gru_layer_kernel<<<gg, 256>>>(WH[1], BH[1], out, 1, YD[1]);
    proj_kernel<<<pg, 256>>>(x, WI[2], BI[2], KK[2], SRC[2]);
    gru_layer_kernel<<<gg, 256>>>(WH[2], BH[2], out, 2, YD[2]);
}